// round 15
// baseline (speedup 1.0000x reference)
#include <cuda_runtime.h>
#include <cstdint>

#define B 16
#define G 128
#define P 8000
#define R 200
#define POS_CAP 66
#define NBINS 1024
#define CAND_CAP 512
#define NB 250            // blocks = proposal chunks of 32; 250*32 = 8000

// ---------------- scratch (no allocations allowed) ----------------
__device__ unsigned long long d_gbest[B * G];
__device__ int d_parg[B * P];
__device__ unsigned long long d_poskeys[B * P];
__device__ unsigned long long d_negkeys[B * P];
__device__ int d_poscount[B];
__device__ int d_negcount[B];
__device__ int d_posidx[B * POS_CAP];
__device__ int d_negidx[B * R];
__device__ int d_matched[B * G];
__device__ volatile unsigned d_bar;

// ---------------- threefry2x32 (exact JAX, partitionable path) ----------
__device__ __forceinline__ uint32_t rotl32(uint32_t v, int d) {
    return (v << d) | (v >> (32 - d));
}

__device__ __forceinline__ void threefry(uint32_t k0, uint32_t k1, uint32_t x0,
                                         uint32_t x1, uint32_t& o0, uint32_t& o1) {
    uint32_t ks2 = k0 ^ k1 ^ 0x1BD11BDAu;
    x0 += k0; x1 += k1;
#define TFR(r) { x0 += x1; x1 = rotl32(x1, r); x1 ^= x0; }
    TFR(13) TFR(15) TFR(26) TFR(6)
    x0 += k1; x1 += ks2 + 1u;
    TFR(17) TFR(29) TFR(16) TFR(24)
    x0 += ks2; x1 += k0 + 2u;
    TFR(13) TFR(15) TFR(26) TFR(6)
    x0 += k0; x1 += k1 + 3u;
    TFR(17) TFR(29) TFR(16) TFR(24)
    x0 += k1; x1 += ks2 + 4u;
    TFR(13) TFR(15) TFR(26) TFR(6)
    x0 += ks2; x1 += k0 + 5u;
#undef TFR
    o0 = x0; o1 = x1;
}

__device__ __forceinline__ void batch_keys(int b, uint32_t& k1a, uint32_t& k1b,
                                           uint32_t& k2a, uint32_t& k2b) {
    uint32_t kb0, kb1;
    threefry(0u, 42u, 0u, (uint32_t)b, kb0, kb1);   // split(key(42), 16)[b]
    threefry(kb0, kb1, 0u, 0u, k1a, k1b);           // split(key_b, 2)[0]
    threefry(kb0, kb1, 0u, 1u, k2a, k2b);           // split(key_b, 2)[1]
}

// u = m * 2^-23, m = (o0^o1)>>9: strictly monotonic in m -> sort on mantissa
__device__ __forceinline__ uint32_t umant(uint32_t ka, uint32_t kb, int p) {
    uint32_t a, c;
    threefry(ka, kb, 0u, (uint32_t)p, a, c);
    return (a ^ c) >> 9;
}

__device__ __forceinline__ uint32_t ford(float f) {
    uint32_t u = __float_as_uint(f);
    return (u & 0x80000000u) ? ~u : (u | 0x80000000u);
}

// ---------------- software grid barrier ----------------
__device__ __forceinline__ void gsync(unsigned target) {
    __syncthreads();
    if (threadIdx.x == 0) {
        __threadfence();
        atomicAdd((unsigned*)&d_bar, 1u);
        while (d_bar < target) __nanosleep(32);
        __threadfence();
    }
    __syncthreads();
}

// ---------------- init: re-zero accumulators each launch ----------------
__global__ void k_init() {
    int i = blockIdx.x * blockDim.x + threadIdx.x;
    if (i == 0) *(unsigned*)&d_bar = 0u;
    if (i < B * G) { d_gbest[i] = 0ull; d_matched[i] = 0; }
    if (i < B) { d_poscount[i] = 0; d_negcount[i] = 0; }
}

// ---------------- persistent main kernel ----------------
// warp w of block c: proposals [32c, 32c+32) of batch w. All blocks do
// identical total work (sum over batches) -> no barrier imbalance.
__global__ __launch_bounds__(512, 3)
void k_main(const float* __restrict__ gt, const int* __restrict__ gcls,
            const float* __restrict__ pr, float* __restrict__ out,
            float* __restrict__ miss_out) {
    __shared__ __align__(16) unsigned char s_raw[34816];  // sg4 32KB | sgl 2KB
    __shared__ int s_ng[16];
    __shared__ int s_T, s_cnt, s_miss;

    int bid = blockIdx.x;
    int tid = threadIdx.x;
    int lane = tid & 31;
    int wid = tid >> 5;

    int b = wid;                 // batch owned by this warp
    int pbase = bid * 32;        // proposal window
    int p = pbase + lane;

    float4* sg4 = (float4*)s_raw;                          // [16][128]
    unsigned char* sgl = (unsigned char*)(s_raw + 32768);  // [16][128]

    // ---------- warp-private GT load + order-preserving compaction ----------
    {
        int ng = 0;
        #pragma unroll
        for (int r = 0; r < 4; ++r) {
            int g = r * 32 + lane;
            const float* gp = gt + ((size_t)b * G + g) * 5;
            float a0 = gp[0], a1 = gp[1], a2 = gp[2], a3 = gp[3];
            bool v = (gp[4] != 0.0f);
            unsigned ball = __ballot_sync(0xFFFFFFFFu, v);
            if (v) {
                int rank = ng + __popc(ball & ((1u << lane) - 1u));
                sg4[wid * G + rank] = make_float4(a0, a1, a2, a3);
                sgl[wid * G + rank] = (unsigned char)g;
            }
            ng += __popc(ball);
        }
        if (lane == 0) s_ng[wid] = ng;
        __syncwarp();
    }
    int ng = s_ng[wid];

    // ---------- phase 1: IoU, per-p argmax (regs) + per-g argmax (warp) ----
    const float* pp = pr + ((size_t)b * P + p) * 5;
    float p0 = pp[0], p1 = pp[1], p2 = pp[2], p3 = pp[3];
    bool pv = (pp[4] != 0.0f);
    float ap = __fmul_rn(__fsub_rn(p3, p1), __fsub_rn(p2, p0));

    float best = -1.0f;
    int barg = 0;
    for (int i = 0; i < ng; ++i) {
        float4 gb = sg4[wid * G + i];
        float ga = __fmul_rn(__fsub_rn(gb.w, gb.y), __fsub_rn(gb.z, gb.x));
        float iw = fmaxf(0.0f, __fsub_rn(fminf(gb.w, p3), fmaxf(gb.y, p1)));
        float ih = fmaxf(0.0f, __fsub_rn(fminf(gb.z, p2), fmaxf(gb.x, p0)));
        float inter = __fmul_rn(iw, ih);
        float denom = __fsub_rn(__fadd_rn(ga, ap), inter);
        float iou = __fdiv_rn(inter, denom);
        float v = pv ? iou : -1.0f;
        if (v > best) { best = v; barg = i; }   // first-index argmax over g

        uint32_t fv = pv ? ford(v) : 0u;        // valid iou >= 0 -> fv != 0
        uint32_t wmax = __reduce_max_sync(0xFFFFFFFFu, fv);
        if (wmax != 0u) {
            uint32_t pc = (fv == wmax) ? (uint32_t)p : 0xFFFFFFFFu;
            uint32_t pmin = __reduce_min_sync(0xFFFFFFFFu, pc);  // lowest p
            if (lane == 0) {
                unsigned long long key = (((unsigned long long)wmax) << 32) |
                                         (unsigned long long)(0xFFFFFFFFu - pmin);
                atomicMax(&d_gbest[(size_t)b * G + sgl[wid * G + i]], key);
            }
        }
    }

    // ---------- phase 2 pre: speculative RNG key write (hides barrier) ----
    bool pos = (best >= 0.5f);
    {
        uint32_t k1a, k1b, k2a, k2b;
        batch_keys(b, k1a, k1b, k2a, k2b);
        unsigned long long pk = 0ull, nk = 0ull;
        if (pv) {
            uint32_t plow = 0xFFFFFFFFu - (uint32_t)p;
            if (pos) {
                uint32_t m = umant(k1a, k1b, p);
                pk = (((unsigned long long)m) << 32) | (unsigned long long)plow;
            } else {
                uint32_t m = umant(k2a, k2b, p);
                nk = (((unsigned long long)m) << 32) | (unsigned long long)plow;
            }
        }
        size_t bp2 = (size_t)b * P + p;
        d_poskeys[bp2] = pk;
        d_negkeys[bp2] = nk;
    }

    gsync(NB);

    // ---------- phase 2 post: removed fixup, counts, matched, parg ----------
    {
        uint32_t mask = 0u;
        #pragma unroll
        for (int r = 0; r < 4; ++r) {
            int g = r * 32 + lane;
            unsigned long long key = d_gbest[(size_t)b * G + g];
            if (key != 0ull) {
                uint32_t arg = 0xFFFFFFFFu - (uint32_t)(key & 0xFFFFFFFFull);
                uint32_t rel = arg - (uint32_t)pbase;
                if (rel < 32u) mask |= (1u << rel);
            }
        }
        mask = __reduce_or_sync(0xFFFFFFFFu, mask);
        bool removed = ((mask >> lane) & 1u) != 0;
        bool keep = pv && !removed;

        size_t bp2 = (size_t)b * P + p;
        if (pv && removed) {
            if (pos) d_poskeys[bp2] = 0ull;
            else     d_negkeys[bp2] = 0ull;
        }
        if (keep && pos) {
            int gg = sgl[wid * G + barg];
            d_matched[b * G + gg] = 1;
            d_parg[bp2] = gg;
        }
        uint32_t bp_ = __ballot_sync(0xFFFFFFFFu, keep && pos);
        uint32_t bn_ = __ballot_sync(0xFFFFFFFFu, keep && !pos);
        if (lane == 0) {
            if (bp_) atomicAdd(&d_poscount[b], __popc(bp_));
            if (bn_) atomicAdd(&d_negcount[b], __popc(bn_));
        }
    }

    gsync(2 * NB);

    // ---------- phase 3: exact top-K select (32 blocks) ----------
    if (bid < 32) {
        uint32_t* hist = (uint32_t*)s_raw;                      // 4KB
        uint32_t* sfx = hist + NBINS;                           // 4KB
        uint32_t* sfx2 = sfx + NBINS;                           // 4KB
        unsigned long long* cand = (unsigned long long*)(sfx2 + NBINS);  // 4KB
        uint32_t* cand_p = (uint32_t*)(cand + CAND_CAP);        // 2KB

        int sb = bid >> 1;
        bool isPos = ((bid & 1) == 0);
        int K = isPos ? POS_CAP : R;
        const unsigned long long* src =
            isPos ? (d_poskeys + (size_t)sb * P) : (d_negkeys + (size_t)sb * P);

        for (int i = tid; i < NBINS; i += 512) hist[i] = 0u;
        if (tid == 0) { s_T = 0; s_cnt = 0; }
        __syncthreads();

        for (int q = tid; q < P; q += 512) {
            unsigned long long key = src[q];
            if (key != 0ull) atomicAdd(&hist[(uint32_t)(key >> 45)], 1u);
        }
        __syncthreads();

        for (int i = tid; i < NBINS; i += 512) sfx[i] = hist[i];
        __syncthreads();
        uint32_t* cur = sfx;
        uint32_t* nxt = sfx2;
        for (int d = 1; d < NBINS; d <<= 1) {
            for (int i = tid; i < NBINS; i += 512) {
                uint32_t v = cur[i];
                if (i + d < NBINS) v += cur[i + d];
                nxt[i] = v;
            }
            __syncthreads();
            uint32_t* t = cur; cur = nxt; nxt = t;
        }

        for (int i = tid; i < NBINS; i += 512) {
            if (cur[i] >= (uint32_t)K && (i == NBINS - 1 || cur[i + 1] < (uint32_t)K))
                s_T = i;
        }
        __syncthreads();
        int T = s_T;

        for (int q = tid; q < P; q += 512) {
            unsigned long long key = src[q];
            if (key != 0ull && (int)(key >> 45) >= T) {
                int pos2 = atomicAdd(&s_cnt, 1);
                if (pos2 < CAND_CAP) { cand[pos2] = key; cand_p[pos2] = (uint32_t)q; }
            }
        }
        __syncthreads();
        int cnt = min(s_cnt, CAND_CAP);

        // rank-by-count (keys distinct): rank r < K -> output slot r
        for (int i = tid; i < cnt; i += 512) {
            unsigned long long ki = cand[i];
            int rank = 0;
            for (int j = 0; j < cnt; ++j) rank += (cand[j] > ki) ? 1 : 0;
            if (rank < K) {
                if (isPos) d_posidx[sb * POS_CAP + rank] = (int)cand_p[i];
                else       d_negidx[sb * R + rank] = (int)cand_p[i];
            }
        }
    }

    gsync(3 * NB);

    // ---------- phase 4: emit outputs (16 blocks) ----------
    if (bid >= B) return;
    int eb = bid;

    if (tid == 0) s_miss = 0;
    __syncthreads();
    if (tid < G) {
        if (gt[((size_t)eb * G + tid) * 5 + 4] != 0.0f && d_matched[eb * G + tid] == 0)
            atomicAdd(&s_miss, 1);
    }

    if (tid < R) {
        int s = tid;
        int np = min(d_poscount[eb], POS_CAP);
        int nn = min(R - np, d_negcount[eb]);

        float de0 = 0, de1 = 0, de2 = 0, de3 = 0, de4 = 0;
        float c0 = 0, c1 = 0;
        float r0 = 0, r1 = 0, r2 = 0, r3 = 0, r4 = 0;

        bool is_pos = s < np;
        bool is_real = s < np + nn;

        if (is_real) {
            int idx = is_pos ? d_posidx[eb * POS_CAP + s] : d_negidx[eb * R + (s - np)];
            const float* q = pr + ((size_t)eb * P + idx) * 5;
            r0 = q[0]; r1 = q[1]; r2 = q[2]; r3 = q[3]; r4 = 1.0f;
            c1 = 1.0f;
            if (is_pos) {
                int g = d_parg[(size_t)eb * P + idx];
                const float* gp = gt + ((size_t)eb * G + g) * 5;
                float g0 = gp[0], g1 = gp[1], g2 = gp[2], g3 = gp[3];
                float h = r2 - r0, w = r3 - r1;
                float gh = g2 - g0, gw = g3 - g1;
                float cy = (r2 + r0) * 0.5f, cx = (r3 + r1) * 0.5f;
                float gcy = (g2 + g0) * 0.5f, gcx = (g3 + g1) * 0.5f;
                de0 = ((gcy - cy) / h) / 0.1f;
                de1 = ((gcx - cx) / w) / 0.1f;
                de2 = logf(fmaxf(gh / h, 1e-8f)) / 0.2f;
                de3 = logf(fmaxf(gw / w, 1e-8f)) / 0.2f;
                de4 = 1.0f;
                c0 = (float)gcls[((size_t)eb * G + g) * 2 + 0];
            } else {
                de4 = -1.0f;
            }
        }

        size_t sl = (size_t)eb * R + s;
        float* dd = out + sl * 5;
        dd[0] = de0; dd[1] = de1; dd[2] = de2; dd[3] = de3; dd[4] = de4;
        float* cc = out + (size_t)B * R * 5 + sl * 2;
        cc[0] = c0; cc[1] = c1;
        float* rr = out + (size_t)B * R * 5 + (size_t)B * R * 2 + sl * 5;
        rr[0] = r0; rr[1] = r1; rr[2] = r2; rr[3] = r3; rr[4] = r4;
    }

    __syncthreads();
    if (tid == 0) miss_out[eb] = (float)s_miss;
}

// ---------------- launch ----------------
extern "C" void kernel_launch(void* const* d_in, const int* in_sizes, int n_in,
                              void* d_out, int out_size) {
    const float* gt = (const float*)d_in[0];
    const int* gcls = (const int*)d_in[1];
    const float* pr = (const float*)d_in[2];
    float* out = (float*)d_out;

    float* miss_out = out + (size_t)B * R * 5 + (size_t)B * R * 2 + (size_t)B * R * 5;

    k_init<<<8, 256>>>();
    k_main<<<NB, 512>>>(gt, gcls, pr, out, miss_out);
}